// round 16
// baseline (speedup 1.0000x reference)
#include <cuda_runtime.h>
#include <cuda_fp16.h>
#include <cstdint>
#include <math.h>
#include <stddef.h>

// Problem constants
#define BB 4
#define SS 2048
#define DD 1024
#define MTOT (BB * SS)          // 8192
#define LN_EPS 1e-5f
#define INV_SCALE 0.125f        // 1/sqrt(64)

// ---------------- scratch (device globals; no allocation allowed) ----------
__device__ __half g_xh   [MTOT * DD];             // fp16(x)
__device__ __half g_WqkvT[3 * DD * DD];           // concat [Wq^T; Wk^T; Wv^T]
__device__ __half g_W1T  [DD * DD];
__device__ __half g_W2T  [DD * DD];
__device__ float  g_bqkv [3 * DD];                // concat biases
__device__ __half g_QKVh [MTOT * 3 * DD];         // [8192, 3072]: Q|K|V
__device__ __half g_Ph   [(size_t)BB * SS * SS];  // exp'd scores fp16 (32 MB)
__device__ float  g_rowpart[16 * MTOT];           // per-(n-block,row) partials
__device__ __half g_Oh   [MTOT * DD];             // attention output (fp16)
__device__ __half g_Hh   [MTOT * DD];             // H residual (fp16)
__device__ __half g_H1h  [MTOT * DD];
__device__ __half g_H2h  [MTOT * DD];             // FFN2 output (fp16)

// ---------------- helpers ---------------------------------------------------
__device__ __forceinline__ uint32_t smem_u32(const void* p) {
    uint32_t a;
    asm("{ .reg .u64 t; cvta.to.shared.u64 t, %1; cvt.u32.u64 %0, t; }" : "=r"(a) : "l"(p));
    return a;
}
__device__ __forceinline__ void cpa16(uint32_t dst, const void* src) {
    asm volatile("cp.async.cg.shared.global [%0], [%1], 16;" :: "r"(dst), "l"(src));
}
#define CP_COMMIT() asm volatile("cp.async.commit_group;" ::: "memory")
#define CP_WAIT1()  asm volatile("cp.async.wait_group 1;" ::: "memory")

__device__ __forceinline__ float gelu_exact(float x) {
    return 0.5f * x * (1.0f + erff(x * 0.70710678118654752f));
}
__device__ __forceinline__ float warp_sum(float v) {
    #pragma unroll
    for (int o = 16; o > 0; o >>= 1) v += __shfl_xor_sync(0xffffffffu, v, o);
    return v;
}

// mma.sync m16n8k16 fp16 inputs, fp32 accum
__device__ __forceinline__ void mma_f16(float* d, const uint32_t* a, const uint32_t* b) {
    asm volatile(
        "mma.sync.aligned.m16n8k16.row.col.f32.f16.f16.f32 "
        "{%0,%1,%2,%3}, {%4,%5,%6,%7}, {%8,%9}, {%0,%1,%2,%3};"
        : "+f"(d[0]), "+f"(d[1]), "+f"(d[2]), "+f"(d[3])
        : "r"(a[0]), "r"(a[1]), "r"(a[2]), "r"(a[3]), "r"(b[0]), "r"(b[1]));
}
__device__ __forceinline__ void ldsm4(uint32_t* r, uint32_t addr) {
    asm volatile("ldmatrix.sync.aligned.m8n8.x4.shared.b16 {%0,%1,%2,%3}, [%4];"
        : "=r"(r[0]), "=r"(r[1]), "=r"(r[2]), "=r"(r[3]) : "r"(addr));
}
__device__ __forceinline__ void ldsm4t(uint32_t* r, uint32_t addr) {
    asm volatile("ldmatrix.sync.aligned.m8n8.x4.trans.shared.b16 {%0,%1,%2,%3}, [%4];"
        : "=r"(r[0]), "=r"(r[1]), "=r"(r[2]), "=r"(r[3]) : "r"(addr));
}
__device__ __forceinline__ __half2 ex2_h2(float a0, float a1) {
    __half2 ah = __floats2half2_rn(a0, a1);
    uint32_t ein = *(uint32_t*)&ah, eout;
    asm("ex2.approx.f16x2 %0, %1;" : "=r"(eout) : "r"(ein));
    return *(__half2*)&eout;
}

// ---------------- fp16 tensor GEMM ------------------------------------------
// TRANSB=0: C[M,N] = A[M,K] @ B^T, B stored [N,K] row-major (K-major).
// TRANSB=1: C[M,N] = A[M,K] @ B,   B stored [K,N] row-major (V natural layout).
// CTA tile 128x128, 128 threads (4 warps), warp tile 64x64, BK=64 halves,
// 3-stage cp.async ring, single-sync load-before-compute pipeline, 2 CTAs/SM.
static constexpr int STAGE_BYTES = (128 + 128) * 64 * 2;        // 32768
static constexpr int SMEM_BYTES  = 3 * STAGE_BYTES + 512;       // + rowinv stash

#define SWB(row, bytecol) ((row) * 128 + (((bytecol) ^ (((row) & 7) << 4))))

// Flags: DOGELU, OUTHALF, DOEXP (exp + row partials), DONORM (scale by 1/rowsum),
//        TRANSB (B in [K,N] layout, ldmatrix.trans path)
template<int DOGELU, int OUTHALF, int DOEXP, int DONORM, int TRANSB>
__global__ __launch_bounds__(128, 2)
void tgemm(const __half* __restrict__ A, const __half* __restrict__ B,
           const float* __restrict__ bias, void* __restrict__ Cv,
           int ldA, int ldB, int ldC, int K, float scale,
           size_t strA, size_t strB, size_t strC, float* __restrict__ aux)
{
    extern __shared__ __align__(1024) char smem[];
    const uint32_t sb = smem_u32(smem);
    float* rowinv = (float*)(smem + 3 * STAGE_BYTES);
    const int tid  = threadIdx.x;
    const int lane = tid & 31;
    const int wid  = tid >> 5;            // 0..3
    const int warpRow = (wid & 1) * 64;
    const int warpCol = (wid >> 1) * 64;

    const int m0 = blockIdx.y * 128;
    const int n0 = blockIdx.x * 128;
    A += (size_t)blockIdx.z * strA + (size_t)m0 * ldA;
    if (TRANSB) B += (size_t)blockIdx.z * strB + n0;          // n = columns
    else        B += (size_t)blockIdx.z * strB + (size_t)n0 * ldB;

    float acc[4][8][4];
    #pragma unroll
    for (int i = 0; i < 4; i++)
        #pragma unroll
        for (int j = 0; j < 8; j++)
            #pragma unroll
            for (int q = 0; q < 4; q++) acc[i][j][q] = 0.0f;

    const int NK = K >> 6;

    const int arow0 = tid >> 3;       // 0..15
    const int aks   = (tid & 7);

    auto load_stage = [&](int kt, int st) {
        const int koff = kt * 64;
        const uint32_t stb = sb + st * STAGE_BYTES;
        #pragma unroll
        for (int i = 0; i < 8; i++) {
            const int row = arow0 + i * 16;
            cpa16(stb + SWB(row, aks * 16),
                  A + (size_t)row * ldA + koff + aks * 8);
        }
        const uint32_t stbB = stb + 16384;
        if (TRANSB) {
            #pragma unroll
            for (int i = 0; i < 8; i++) {
                const int seg = tid + i * 128;      // 0..1023
                const int row = seg >> 4;           // 0..63 (k)
                const int cg  = seg & 15;           // 16B col group (n)
                cpa16(stbB + row * 256 + ((cg * 16) ^ ((row & 7) << 4)),
                      B + (size_t)(koff + row) * ldB + cg * 8);
            }
        } else {
            #pragma unroll
            for (int i = 0; i < 8; i++) {
                const int row = arow0 + i * 16;
                cpa16(stbB + SWB(row, aks * 16),
                      B + (size_t)row * ldB + koff + aks * 8);
            }
        }
        CP_COMMIT();
    };

    load_stage(0, 0);
    if (NK > 1) load_stage(1, 1);

    // rowsum prologue (PV): reduce 16 partials -> 1/rowsum in smem stash
    if (DONORM) {
        float s = 0.0f;
        #pragma unroll
        for (int i = 0; i < 16; i++)
            s += aux[(size_t)i * MTOT + blockIdx.z * SS + m0 + tid];
        rowinv[tid] = 1.0f / s;
    }

    const int sub = lane >> 3;
    const int l7  = lane & 7;
    uint32_t aoff[4], boff[4];
    {
        const int arow = l7 + (sub & 1) * 8;
        const int acolB = (sub >> 1) * 16;
        #pragma unroll
        for (int ma = 0; ma < 4; ma++)
            aoff[ma] = SWB(warpRow + ma * 16 + arow, acolB);
        if (TRANSB) {
            const int brow = l7 + (sub & 1) * 8;       // k row within 16
            #pragma unroll
            for (int p = 0; p < 4; p++) {
                const int ncol = warpCol + p * 16 + (sub >> 1) * 8;
                boff[p] = brow * 256 + (((uint32_t)(ncol * 2)) ^ ((l7 & 7) << 4));
            }
        } else {
            const int brow = l7 + (sub >> 1) * 8;
            const int bcolB = (sub & 1) * 16;
            #pragma unroll
            for (int p = 0; p < 4; p++)
                boff[p] = SWB(warpCol + p * 16 + brow, bcolB);
        }
    }

    auto compute_stage = [&](int st) {
        const uint32_t stbA = sb + st * STAGE_BYTES;
        const uint32_t stbB = stbA + 16384;
        #pragma unroll
        for (int kk = 0; kk < 4; kk++) {
            const uint32_t kx = kk * 32;
            uint32_t af[4][4];
            #pragma unroll
            for (int ma = 0; ma < 4; ma++)
                ldsm4(af[ma], stbA + (aoff[ma] ^ kx));
            uint32_t bf[4][4];
            if (TRANSB) {
                #pragma unroll
                for (int p = 0; p < 4; p++)
                    ldsm4t(bf[p], stbB + boff[p] + kk * 4096);
            } else {
                #pragma unroll
                for (int p = 0; p < 4; p++)
                    ldsm4(bf[p], stbB + (boff[p] ^ kx));
            }
            #pragma unroll
            for (int ma = 0; ma < 4; ma++)
                #pragma unroll
                for (int nb = 0; nb < 8; nb++)
                    mma_f16(acc[ma][nb], af[ma], &bf[nb >> 1][(nb & 1) * 2]);
        }
    };

    // single-sync pipeline: wait(kt) ; sync ; prefetch(kt+2) ; compute(kt)
    int st = 0, stn = 2;                 // stage of kt, stage of kt+2
    for (int kt = 0; kt < NK; kt++) {
        CP_WAIT1();
        __syncthreads();
        if (kt + 2 < NK) load_stage(kt + 2, stn);
        compute_stage(st);
        st  = (st  == 2) ? 0 : st  + 1;
        stn = (stn == 2) ? 0 : stn + 1;
    }

    // ---- epilogue ----
    const int r_lo = lane >> 2;
    const int c_lo = lane & 3;
    const float L2E = 1.4426950408889634f;

    if (DOEXP) {
        __half* C = (__half*)Cv + strC * blockIdx.z;
        float rsum[4][2];
        #pragma unroll
        for (int ma = 0; ma < 4; ma++) { rsum[ma][0] = 0.0f; rsum[ma][1] = 0.0f; }
        #pragma unroll
        for (int ma = 0; ma < 4; ma++) {
            const int r0 = m0 + warpRow + ma * 16 + r_lo;
            const int r1 = r0 + 8;
            #pragma unroll
            for (int nb = 0; nb < 8; nb++) {
                const int col = n0 + warpCol + nb * 8 + c_lo * 2;
                float v0 = fminf(acc[ma][nb][0] * scale, 11.0f);
                float v1 = fminf(acc[ma][nb][1] * scale, 11.0f);
                float v2 = fminf(acc[ma][nb][2] * scale, 11.0f);
                float v3 = fminf(acc[ma][nb][3] * scale, 11.0f);
                __half2 e01 = ex2_h2(v0 * L2E, v1 * L2E);
                __half2 e23 = ex2_h2(v2 * L2E, v3 * L2E);
                *(__half2*)&C[(size_t)r0 * ldC + col] = e01;
                *(__half2*)&C[(size_t)r1 * ldC + col] = e23;
                float2 f01 = __half22float2(e01);
                float2 f23 = __half22float2(e23);
                rsum[ma][0] += f01.x + f01.y;
                rsum[ma][1] += f23.x + f23.y;
            }
        }
        __syncthreads();             // all compute done before smem reuse
        float* sfp = (float*)smem;   // stage smem no longer needed
        #pragma unroll
        for (int ma = 0; ma < 4; ma++)
            #pragma unroll
            for (int h = 0; h < 2; h++) {
                float s = rsum[ma][h];
                s += __shfl_xor_sync(0xffffffffu, s, 1);
                s += __shfl_xor_sync(0xffffffffu, s, 2);
                if (c_lo == 0)
                    sfp[(warpRow + ma * 16 + r_lo + h * 8) * 2 + (wid >> 1)] = s;
            }
        __syncthreads();
        if (tid < 128) {
            float t = sfp[tid * 2] + sfp[tid * 2 + 1];
            aux[(size_t)blockIdx.x * MTOT + blockIdx.z * SS + m0 + tid] = t;
        }
        return;
    }

    #pragma unroll
    for (int ma = 0; ma < 4; ma++) {
        const int r0 = m0 + warpRow + ma * 16 + r_lo;
        const int r1 = r0 + 8;
        float inv0 = 1.0f, inv1 = 1.0f;
        if (DONORM) {
            inv0 = rowinv[warpRow + ma * 16 + r_lo];
            inv1 = rowinv[warpRow + ma * 16 + r_lo + 8];
        }
        #pragma unroll
        for (int nb = 0; nb < 8; nb++) {
            const int col = n0 + warpCol + nb * 8 + c_lo * 2;
            float b0 = 0.0f, b1 = 0.0f;
            if (bias) {
                float2 bv = *(const float2*)&bias[col];
                b0 = bv.x; b1 = bv.y;
            }
            float v0 = acc[ma][nb][0] * scale + b0;
            float v1 = acc[ma][nb][1] * scale + b1;
            float v2 = acc[ma][nb][2] * scale + b0;
            float v3 = acc[ma][nb][3] * scale + b1;
            if (DONORM) { v0 *= inv0; v1 *= inv0; v2 *= inv1; v3 *= inv1; }
            if (DOGELU) {
                v0 = gelu_exact(v0); v1 = gelu_exact(v1);
                v2 = gelu_exact(v2); v3 = gelu_exact(v3);
            }
            if (OUTHALF) {
                __half* C = (__half*)Cv + strC * blockIdx.z;
                *(__half2*)&C[(size_t)r0 * ldC + col] =
                    __halves2half2(__float2half_rn(v0), __float2half_rn(v1));
                *(__half2*)&C[(size_t)r1 * ldC + col] =
                    __halves2half2(__float2half_rn(v2), __float2half_rn(v3));
            } else {
                float* C = (float*)Cv + strC * blockIdx.z;
                *(float2*)&C[(size_t)r0 * ldC + col] = make_float2(v0, v1);
                *(float2*)&C[(size_t)r1 * ldC + col] = make_float2(v2, v3);
            }
        }
    }
}

// ---------------- prep: transposes + x->fp16 + bias concat (one launch) -----
__global__ __launch_bounds__(256)
void prep(const float* __restrict__ x,
          const float* __restrict__ Wq, const float* __restrict__ Wk,
          const float* __restrict__ Wv, const float* __restrict__ W1,
          const float* __restrict__ W2,
          const float* __restrict__ bq, const float* __restrict__ bk,
          const float* __restrict__ bv,
          __half* __restrict__ xh, __half* __restrict__ WqkvT,
          __half* __restrict__ W1T, __half* __restrict__ W2T,
          float* __restrict__ bqkv)
{
    const int bid = blockIdx.x;
    const int tid = threadIdx.x;
    if (bid < 5120) {
        __shared__ float tile[32][33];
        const int z = bid >> 10;
        const int t = bid & 1023;
        const int c0 = (t & 31) * 32, r0 = (t >> 5) * 32;
        const float* in = (z == 0) ? Wq : (z == 1) ? Wk : (z == 2) ? Wv : (z == 3) ? W1 : W2;
        __half* out = (z == 0) ? WqkvT : (z == 1) ? (WqkvT + DD * DD)
                     : (z == 2) ? (WqkvT + 2 * DD * DD) : (z == 3) ? W1T : W2T;
        const int tx = tid & 31, ty = tid >> 5;   // 32 x 8
        #pragma unroll
        for (int i = 0; i < 4; i++)
            tile[ty + i * 8][tx] = in[(size_t)(r0 + ty + i * 8) * DD + c0 + tx];
        __syncthreads();
        #pragma unroll
        for (int i = 0; i < 4; i++)
            out[(size_t)(c0 + ty + i * 8) * DD + r0 + tx] =
                __float2half_rn(tile[tx][ty + i * 8]);
    } else if (bid < 13312) {
        size_t i = (size_t)(bid - 5120) * 256 + tid;     // float4 index
        float4 v = ((const float4*)x)[i];
        ((__half2*)xh)[i * 2]     = __halves2half2(__float2half_rn(v.x), __float2half_rn(v.y));
        ((__half2*)xh)[i * 2 + 1] = __halves2half2(__float2half_rn(v.z), __float2half_rn(v.w));
    } else {
        const int z = bid - 13312;
        const float* src = (z == 0) ? bq : (z == 1) ? bk : bv;
        for (int i = tid; i < DD; i += 256) bqkv[z * DD + i] = src[i];
    }
}

// final: out = LN(h2 + h) with fp16 inputs, fp32 math + output
__global__ __launch_bounds__(256)
void add_ln1024_hh(const __half* __restrict__ A, const __half* __restrict__ R,
                   const float* __restrict__ gamma, const float* __restrict__ beta,
                   float* __restrict__ out)
{
    const size_t row = blockIdx.x;
    const int t = threadIdx.x, lane = t & 31, wid = t >> 5;
    __shared__ float rs[8], rq[8];

    uint2 ar = ((const uint2*)(A + row * 1024))[t];
    uint2 rr = ((const uint2*)(R + row * 1024))[t];
    float2 a01 = __half22float2(*(__half2*)&ar.x);
    float2 a23 = __half22float2(*(__half2*)&ar.y);
    float2 r01 = __half22float2(*(__half2*)&rr.x);
    float2 r23 = __half22float2(*(__half2*)&rr.y);
    float h0 = a01.x + r01.x, h1 = a01.y + r01.y;
    float h2 = a23.x + r23.x, h3 = a23.y + r23.y;

    float s = h0 + h1 + h2 + h3;
    float q = h0 * h0 + h1 * h1 + h2 * h2 + h3 * h3;
    s = warp_sum(s); q = warp_sum(q);
    if (lane == 0) { rs[wid] = s; rq[wid] = q; }
    __syncthreads();
    s = rs[0]; q = rq[0];
    #pragma unroll
    for (int i = 1; i < 8; i++) { s += rs[i]; q += rq[i]; }

    const float mean = s * (1.0f / 1024.0f);
    const float var  = q * (1.0f / 1024.0f) - mean * mean;
    const float rstd = rsqrtf(var + LN_EPS);

    float4 gg = ((const float4*)gamma)[t];
    float4 bb = ((const float4*)beta)[t];
    float4 o;
    o.x = (h0 - mean) * rstd * gg.x + bb.x;
    o.y = (h1 - mean) * rstd * gg.y + bb.y;
    o.z = (h2 - mean) * rstd * gg.z + bb.z;
    o.w = (h3 - mean) * rstd * gg.w + bb.w;
    ((float4*)(out + row * 1024))[t] = o;
}

// fused: at = LN(Oh + xh)*gat+bat; Hh = fp16(LN(at + xh)*gln+bln)
// (x residual read as fp16 — saves 16 MB DRAM vs fp32 x)
__global__ __launch_bounds__(256)
void ln2_fused(const __half* __restrict__ Oh, const __half* __restrict__ Xh,
               const float* __restrict__ gat, const float* __restrict__ bat,
               const float* __restrict__ gln, const float* __restrict__ bln,
               __half* __restrict__ Hh)
{
    const size_t row = blockIdx.x;
    const int t = threadIdx.x, lane = t & 31, wid = t >> 5;
    __shared__ float rs[8], rq[8];

    uint2 orr = ((const uint2*)(Oh + row * 1024))[t];
    uint2 xrr = ((const uint2*)(Xh + row * 1024))[t];
    float2 o01 = __half22float2(*(__half2*)&orr.x);
    float2 o23 = __half22float2(*(__half2*)&orr.y);
    float2 x01 = __half22float2(*(__half2*)&xrr.x);
    float2 x23 = __half22float2(*(__half2*)&xrr.y);
    float xv[4] = {x01.x, x01.y, x23.x, x23.y};
    float h[4] = {o01.x + xv[0], o01.y + xv[1], o23.x + xv[2], o23.y + xv[3]};

    float s = h[0] + h[1] + h[2] + h[3];
    float q = h[0]*h[0] + h[1]*h[1] + h[2]*h[2] + h[3]*h[3];
    s = warp_sum(s); q = warp_sum(q);
    if (lane == 0) { rs[wid] = s; rq[wid] = q; }
    __syncthreads();
    s = rs[0]; q = rq[0];
    #pragma unroll
    for (int i = 1; i < 8; i++) { s += rs[i]; q += rq[i]; }
    float mean = s * (1.0f / 1024.0f);
    float var  = q * (1.0f / 1024.0f) - mean * mean;
    float rstd = rsqrtf(var + LN_EPS);

    float4 g1 = ((const float4*)gat)[t];
    float4 b1 = ((const float4*)bat)[t];
    float u[4];
    u[0] = (h[0] - mean) * rstd * g1.x + b1.x + xv[0];
    u[1] = (h[1] - mean) * rstd * g1.y + b1.y + xv[1];
    u[2] = (h[2] - mean) * rstd * g1.z + b1.z + xv[2];
    u[3] = (h[3] - mean) * rstd * g1.w + b1.w + xv[3];
    __syncthreads();

    s = u[0] + u[1] + u[2] + u[3];
    q = u[0]*u[0] + u[1]*u[1] + u[2]*u[2] + u[3]*u[3];
    s = warp_sum(s); q = warp_sum(q);
    if (lane == 0) { rs[wid] = s; rq[wid] = q; }
    __syncthreads();
    s = rs[0]; q = rq[0];
    #pragma unroll
    for (int i = 1; i < 8; i++) { s += rs[i]; q += rq[i]; }
    mean = s * (1.0f / 1024.0f);
    var  = q * (1.0f / 1024.0f) - mean * mean;
    rstd = rsqrtf(var + LN_EPS);

    float4 g2 = ((const float4*)gln)[t];
    float4 b2 = ((const float4*)bln)[t];
    float v0 = (u[0] - mean) * rstd * g2.x + b2.x;
    float v1 = (u[1] - mean) * rstd * g2.y + b2.y;
    float v2 = (u[2] - mean) * rstd * g2.z + b2.z;
    float v3 = (u[3] - mean) * rstd * g2.w + b2.w;
    uint2 hw;
    __half2 p01 = __halves2half2(__float2half_rn(v0), __float2half_rn(v1));
    __half2 p23 = __halves2half2(__float2half_rn(v2), __float2half_rn(v3));
    hw.x = *(uint32_t*)&p01; hw.y = *(uint32_t*)&p23;
    ((uint2*)(Hh + row * 1024))[t] = hw;
}

// ---------------- launcher ---------------------------------------------------
extern "C" void kernel_launch(void* const* d_in, const int* in_sizes, int n_in,
                              void* d_out, int out_size)
{
    const float* x   = (const float*)d_in[0];
    const float* Wq  = (const float*)d_in[1];
    const float* bq  = (const float*)d_in[2];
    const float* Wk  = (const float*)d_in[3];
    const float* bk  = (const float*)d_in[4];
    const float* Wv  = (const float*)d_in[5];
    const float* bv  = (const float*)d_in[6];
    const float* gat = (const float*)d_in[7];
    const float* bat = (const float*)d_in[8];
    const float* gln = (const float*)d_in[9];
    const float* bln = (const float*)d_in[10];
    const float* W1  = (const float*)d_in[11];
    const float* c1  = (const float*)d_in[12];
    const float* W2  = (const float*)d_in[13];
    const float* c2  = (const float*)d_in[14];
    float* out = (float*)d_out;

    __half *xh, *WqkvT, *W1T, *W2T, *QKVh, *Ph, *Oh, *Hh, *H1h, *H2h;
    float *bqkv, *rowpart;
    cudaGetSymbolAddress((void**)&xh,     g_xh);
    cudaGetSymbolAddress((void**)&WqkvT,  g_WqkvT);
    cudaGetSymbolAddress((void**)&W1T,    g_W1T);
    cudaGetSymbolAddress((void**)&W2T,    g_W2T);
    cudaGetSymbolAddress((void**)&bqkv,   g_bqkv);
    cudaGetSymbolAddress((void**)&QKVh,   g_QKVh);
    cudaGetSymbolAddress((void**)&Ph,     g_Ph);
    cudaGetSymbolAddress((void**)&rowpart,g_rowpart);
    cudaGetSymbolAddress((void**)&Oh,     g_Oh);
    cudaGetSymbolAddress((void**)&Hh,     g_Hh);
    cudaGetSymbolAddress((void**)&H1h,    g_H1h);
    cudaGetSymbolAddress((void**)&H2h,    g_H2h);

    cudaFuncSetAttribute(tgemm<0,1,0,0,0>, cudaFuncAttributeMaxDynamicSharedMemorySize, SMEM_BYTES);
    cudaFuncSetAttribute(tgemm<0,1,1,0,0>, cudaFuncAttributeMaxDynamicSharedMemorySize, SMEM_BYTES);
    cudaFuncSetAttribute(tgemm<0,1,0,1,1>, cudaFuncAttributeMaxDynamicSharedMemorySize, SMEM_BYTES);
    cudaFuncSetAttribute(tgemm<1,1,0,0,0>, cudaFuncAttributeMaxDynamicSharedMemorySize, SMEM_BYTES);

    const dim3 blk(256);
    const dim3 gblk(128);
    const size_t sSS = (size_t)SS * SS;

    // 1: prep (x->fp16, W transposes -> WqkvT/W1T/W2T, bias concat)
    prep<<<13315, blk>>>(x, Wq, Wk, Wv, W1, W2, bq, bk, bv,
                         xh, WqkvT, W1T, W2T, bqkv);

    // 2: merged QKV GEMM: [8192,3072] = xh @ WqkvT^T + bqkv
    tgemm<0,1,0,0,0><<<dim3(24, 64, 1), gblk, SMEM_BYTES>>>(
        xh, WqkvT, bqkv, QKVh, DD, DD, 3 * DD, DD, 1.0f, 0, 0, 0, nullptr);

    const __half* Qh = QKVh;
    const __half* Kh = QKVh + DD;
    const __half* Vh = QKVh + 2 * DD;

    // 3: scores GEMM with fused exp + row partials -> Ph (exp'd fp16)
    tgemm<0,1,1,0,0><<<dim3(16, 16, BB), gblk, SMEM_BYTES>>>(
        Qh, Kh, nullptr, Ph, 3 * DD, 3 * DD, SS, DD, INV_SCALE,
        (size_t)SS * 3 * DD, (size_t)SS * 3 * DD, sSS, rowpart);

    // 4: Oh = (Pexp @ V) / rowsum (fp16 out; V natural layout via ldmatrix.trans)
    tgemm<0,1,0,1,1><<<dim3(8, 16, BB), gblk, SMEM_BYTES>>>(
        Ph, Vh, nullptr, Oh, SS, 3 * DD, DD, SS, 1.0f,
        sSS, (size_t)SS * 3 * DD, (size_t)SS * DD, rowpart);

    // 5: fused double-LN -> Hh (fp16 in/out; x residual from xh)
    ln2_fused<<<MTOT, blk>>>(Oh, xh, gat, bat, gln, bln, Hh);

    // 6-7: FFN (launch idx 5 = FFN1 -> profiled by ncu -s 5 -c 1)
    tgemm<1,1,0,0,0><<<dim3(8, 64, 1), gblk, SMEM_BYTES>>>(
        Hh,  W1T, c1, H1h, DD, DD, DD, DD, 1.0f, 0, 0, 0, nullptr);
    tgemm<1,1,0,0,0><<<dim3(8, 64, 1), gblk, SMEM_BYTES>>>(
        H1h, W2T, c2, H2h, DD, DD, DD, DD, 1.0f, 0, 0, 0, nullptr);

    // 8: out = LN(h2 + h), fp16 inputs, fp32 output
    add_ln1024_hh<<<MTOT, blk>>>(H2h, Hh, gln, bln, out);
}

// round 17
// speedup vs baseline: 1.0129x; 1.0129x over previous
#include <cuda_runtime.h>
#include <cuda_fp16.h>
#include <cstdint>
#include <math.h>
#include <stddef.h>

// Problem constants
#define BB 4
#define SS 2048
#define DD 1024
#define MTOT (BB * SS)          // 8192
#define LN_EPS 1e-5f
#define INV_SCALE 0.125f        // 1/sqrt(64)

// ---------------- scratch (device globals; no allocation allowed) ----------
__device__ __half g_xh   [MTOT * DD];             // fp16(x)
__device__ __half g_WqkvT[3 * DD * DD];           // concat [Wq^T; Wk^T; Wv^T]
__device__ __half g_W1T  [DD * DD];
__device__ __half g_W2T  [DD * DD];
__device__ float  g_bqkv [3 * DD];                // concat biases
__device__ __half g_QKVh [MTOT * 3 * DD];         // [8192, 3072]: Q|K|V
__device__ __half g_Ph   [(size_t)BB * SS * SS];  // exp'd scores fp16 (32 MB)
__device__ float  g_rowpart[16 * MTOT];           // per-(n-block,row) partials
__device__ __half g_Oh   [MTOT * DD];             // attention output (fp16)
__device__ __half g_Hh   [MTOT * DD];             // H residual (fp16)
__device__ __half g_H1h  [MTOT * DD];
__device__ __half g_H2h  [MTOT * DD];             // FFN2 output (fp16)

// ---------------- helpers ---------------------------------------------------
__device__ __forceinline__ uint32_t smem_u32(const void* p) {
    uint32_t a;
    asm("{ .reg .u64 t; cvta.to.shared.u64 t, %1; cvt.u32.u64 %0, t; }" : "=r"(a) : "l"(p));
    return a;
}
__device__ __forceinline__ void cpa16(uint32_t dst, const void* src) {
    asm volatile("cp.async.cg.shared.global [%0], [%1], 16;" :: "r"(dst), "l"(src));
}
#define CP_COMMIT() asm volatile("cp.async.commit_group;" ::: "memory")
#define CP_WAIT1()  asm volatile("cp.async.wait_group 1;" ::: "memory")

__device__ __forceinline__ float gelu_exact(float x) {
    return 0.5f * x * (1.0f + erff(x * 0.70710678118654752f));
}
__device__ __forceinline__ float warp_sum(float v) {
    #pragma unroll
    for (int o = 16; o > 0; o >>= 1) v += __shfl_xor_sync(0xffffffffu, v, o);
    return v;
}

// mma.sync m16n8k16 fp16 inputs, fp32 accum
__device__ __forceinline__ void mma_f16(float* d, const uint32_t* a, const uint32_t* b) {
    asm volatile(
        "mma.sync.aligned.m16n8k16.row.col.f32.f16.f16.f32 "
        "{%0,%1,%2,%3}, {%4,%5,%6,%7}, {%8,%9}, {%0,%1,%2,%3};"
        : "+f"(d[0]), "+f"(d[1]), "+f"(d[2]), "+f"(d[3])
        : "r"(a[0]), "r"(a[1]), "r"(a[2]), "r"(a[3]), "r"(b[0]), "r"(b[1]));
}
__device__ __forceinline__ void ldsm4(uint32_t* r, uint32_t addr) {
    asm volatile("ldmatrix.sync.aligned.m8n8.x4.shared.b16 {%0,%1,%2,%3}, [%4];"
        : "=r"(r[0]), "=r"(r[1]), "=r"(r[2]), "=r"(r[3]) : "r"(addr));
}
__device__ __forceinline__ void ldsm4t(uint32_t* r, uint32_t addr) {
    asm volatile("ldmatrix.sync.aligned.m8n8.x4.trans.shared.b16 {%0,%1,%2,%3}, [%4];"
        : "=r"(r[0]), "=r"(r[1]), "=r"(r[2]), "=r"(r[3]) : "r"(addr));
}
__device__ __forceinline__ __half2 ex2_h2(float a0, float a1) {
    __half2 ah = __floats2half2_rn(a0, a1);
    uint32_t ein = *(uint32_t*)&ah, eout;
    asm("ex2.approx.f16x2 %0, %1;" : "=r"(eout) : "r"(ein));
    return *(__half2*)&eout;
}

// ---------------- fp16 tensor GEMM ------------------------------------------
// TRANSB=0: C[M,N] = A[M,K] @ B^T, B stored [N,K] row-major (K-major).
// TRANSB=1: C[M,N] = A[M,K] @ B,   B stored [K,N] row-major (V natural layout).
// CTA tile 128x128, 128 threads (4 warps), warp tile 64x64, BK=64 halves,
// 3-stage cp.async ring, single-sync load-before-compute pipeline, 2 CTAs/SM.
static constexpr int STAGE_BYTES = (128 + 128) * 64 * 2;        // 32768
static constexpr int SMEM_BYTES  = 3 * STAGE_BYTES + 512;       // + rowinv stash

#define SWB(row, bytecol) ((row) * 128 + (((bytecol) ^ (((row) & 7) << 4))))

// Flags: DOGELU, OUTHALF, DOEXP (exp + row partials), DONORM (scale by 1/rowsum),
//        TRANSB (B in [K,N] layout, ldmatrix.trans path)
template<int DOGELU, int OUTHALF, int DOEXP, int DONORM, int TRANSB>
__global__ __launch_bounds__(128, 2)
void tgemm(const __half* __restrict__ A, const __half* __restrict__ B,
           const float* __restrict__ bias, void* __restrict__ Cv,
           int ldA, int ldB, int ldC, int K, float scale,
           size_t strA, size_t strB, size_t strC, float* __restrict__ aux)
{
    extern __shared__ __align__(1024) char smem[];
    const uint32_t sb = smem_u32(smem);
    float* rowinv = (float*)(smem + 3 * STAGE_BYTES);
    const int tid  = threadIdx.x;
    const int lane = tid & 31;
    const int wid  = tid >> 5;            // 0..3
    const int warpRow = (wid & 1) * 64;
    const int warpCol = (wid >> 1) * 64;

    const int m0 = blockIdx.y * 128;
    const int n0 = blockIdx.x * 128;
    A += (size_t)blockIdx.z * strA + (size_t)m0 * ldA;
    if (TRANSB) B += (size_t)blockIdx.z * strB + n0;          // n = columns
    else        B += (size_t)blockIdx.z * strB + (size_t)n0 * ldB;

    float acc[4][8][4];
    #pragma unroll
    for (int i = 0; i < 4; i++)
        #pragma unroll
        for (int j = 0; j < 8; j++)
            #pragma unroll
            for (int q = 0; q < 4; q++) acc[i][j][q] = 0.0f;

    const int NK = K >> 6;

    const int arow0 = tid >> 3;       // 0..15
    const int aks   = (tid & 7);

    auto load_stage = [&](int kt, int st) {
        const int koff = kt * 64;
        const uint32_t stb = sb + st * STAGE_BYTES;
        #pragma unroll
        for (int i = 0; i < 8; i++) {
            const int row = arow0 + i * 16;
            cpa16(stb + SWB(row, aks * 16),
                  A + (size_t)row * ldA + koff + aks * 8);
        }
        const uint32_t stbB = stb + 16384;
        if (TRANSB) {
            #pragma unroll
            for (int i = 0; i < 8; i++) {
                const int seg = tid + i * 128;      // 0..1023
                const int row = seg >> 4;           // 0..63 (k)
                const int cg  = seg & 15;           // 16B col group (n)
                cpa16(stbB + row * 256 + ((cg * 16) ^ ((row & 7) << 4)),
                      B + (size_t)(koff + row) * ldB + cg * 8);
            }
        } else {
            #pragma unroll
            for (int i = 0; i < 8; i++) {
                const int row = arow0 + i * 16;
                cpa16(stbB + SWB(row, aks * 16),
                      B + (size_t)row * ldB + koff + aks * 8);
            }
        }
        CP_COMMIT();
    };

    load_stage(0, 0);
    if (NK > 1) load_stage(1, 1);

    // rowsum prologue (PV): reduce 16 partials -> 1/rowsum in smem stash
    if (DONORM) {
        float s = 0.0f;
        #pragma unroll
        for (int i = 0; i < 16; i++)
            s += aux[(size_t)i * MTOT + blockIdx.z * SS + m0 + tid];
        rowinv[tid] = 1.0f / s;
    }

    const int sub = lane >> 3;
    const int l7  = lane & 7;
    uint32_t aoff[4], boff[4];
    {
        const int arow = l7 + (sub & 1) * 8;
        const int acolB = (sub >> 1) * 16;
        #pragma unroll
        for (int ma = 0; ma < 4; ma++)
            aoff[ma] = SWB(warpRow + ma * 16 + arow, acolB);
        if (TRANSB) {
            const int brow = l7 + (sub & 1) * 8;       // k row within 16
            #pragma unroll
            for (int p = 0; p < 4; p++) {
                const int ncol = warpCol + p * 16 + (sub >> 1) * 8;
                boff[p] = brow * 256 + (((uint32_t)(ncol * 2)) ^ ((l7 & 7) << 4));
            }
        } else {
            const int brow = l7 + (sub >> 1) * 8;
            const int bcolB = (sub & 1) * 16;
            #pragma unroll
            for (int p = 0; p < 4; p++)
                boff[p] = SWB(warpCol + p * 16 + brow, bcolB);
        }
    }

    // single-sync pipeline: wait(kt) ; sync ; prefetch(kt+2) ; compute(kt)
    for (int kt = 0; kt < NK; kt++) {
        CP_WAIT1();
        __syncthreads();

        if (kt + 2 < NK) load_stage(kt + 2, (kt + 2) % 3);

        const uint32_t stbA = sb + (kt % 3) * STAGE_BYTES;
        const uint32_t stbB = stbA + 16384;

        #pragma unroll
        for (int kk = 0; kk < 4; kk++) {
            const uint32_t kx = kk * 32;
            uint32_t af[4][4];
            #pragma unroll
            for (int ma = 0; ma < 4; ma++)
                ldsm4(af[ma], stbA + (aoff[ma] ^ kx));
            uint32_t bf[4][4];
            if (TRANSB) {
                #pragma unroll
                for (int p = 0; p < 4; p++)
                    ldsm4t(bf[p], stbB + boff[p] + kk * 4096);
            } else {
                #pragma unroll
                for (int p = 0; p < 4; p++)
                    ldsm4(bf[p], stbB + (boff[p] ^ kx));
            }
            #pragma unroll
            for (int ma = 0; ma < 4; ma++)
                #pragma unroll
                for (int nb = 0; nb < 8; nb++)
                    mma_f16(acc[ma][nb], af[ma], &bf[nb >> 1][(nb & 1) * 2]);
        }
    }

    // ---- epilogue ----
    const int r_lo = lane >> 2;
    const int c_lo = lane & 3;
    const float L2E = 1.4426950408889634f;

    if (DOEXP) {
        __half* C = (__half*)Cv + strC * blockIdx.z;
        float rsum[4][2];
        #pragma unroll
        for (int ma = 0; ma < 4; ma++) { rsum[ma][0] = 0.0f; rsum[ma][1] = 0.0f; }
        #pragma unroll
        for (int ma = 0; ma < 4; ma++) {
            const int r0 = m0 + warpRow + ma * 16 + r_lo;
            const int r1 = r0 + 8;
            #pragma unroll
            for (int nb = 0; nb < 8; nb++) {
                const int col = n0 + warpCol + nb * 8 + c_lo * 2;
                float v0 = fminf(acc[ma][nb][0] * scale, 11.0f);
                float v1 = fminf(acc[ma][nb][1] * scale, 11.0f);
                float v2 = fminf(acc[ma][nb][2] * scale, 11.0f);
                float v3 = fminf(acc[ma][nb][3] * scale, 11.0f);
                __half2 e01 = ex2_h2(v0 * L2E, v1 * L2E);
                __half2 e23 = ex2_h2(v2 * L2E, v3 * L2E);
                *(__half2*)&C[(size_t)r0 * ldC + col] = e01;
                *(__half2*)&C[(size_t)r1 * ldC + col] = e23;
                float2 f01 = __half22float2(e01);
                float2 f23 = __half22float2(e23);
                rsum[ma][0] += f01.x + f01.y;
                rsum[ma][1] += f23.x + f23.y;
            }
        }
        __syncthreads();             // all compute done before smem reuse
        float* sfp = (float*)smem;   // stage smem no longer needed
        #pragma unroll
        for (int ma = 0; ma < 4; ma++)
            #pragma unroll
            for (int h = 0; h < 2; h++) {
                float s = rsum[ma][h];
                s += __shfl_xor_sync(0xffffffffu, s, 1);
                s += __shfl_xor_sync(0xffffffffu, s, 2);
                if (c_lo == 0)
                    sfp[(warpRow + ma * 16 + r_lo + h * 8) * 2 + (wid >> 1)] = s;
            }
        __syncthreads();
        if (tid < 128) {
            float t = sfp[tid * 2] + sfp[tid * 2 + 1];
            aux[(size_t)blockIdx.x * MTOT + blockIdx.z * SS + m0 + tid] = t;
        }
        return;
    }

    #pragma unroll
    for (int ma = 0; ma < 4; ma++) {
        const int r0 = m0 + warpRow + ma * 16 + r_lo;
        const int r1 = r0 + 8;
        float inv0 = 1.0f, inv1 = 1.0f;
        if (DONORM) {
            inv0 = rowinv[warpRow + ma * 16 + r_lo];
            inv1 = rowinv[warpRow + ma * 16 + r_lo + 8];
        }
        #pragma unroll
        for (int nb = 0; nb < 8; nb++) {
            const int col = n0 + warpCol + nb * 8 + c_lo * 2;
            float b0 = 0.0f, b1 = 0.0f;
            if (bias) {
                float2 bv = *(const float2*)&bias[col];
                b0 = bv.x; b1 = bv.y;
            }
            float v0 = acc[ma][nb][0] * scale + b0;
            float v1 = acc[ma][nb][1] * scale + b1;
            float v2 = acc[ma][nb][2] * scale + b0;
            float v3 = acc[ma][nb][3] * scale + b1;
            if (DONORM) { v0 *= inv0; v1 *= inv0; v2 *= inv1; v3 *= inv1; }
            if (DOGELU) {
                v0 = gelu_exact(v0); v1 = gelu_exact(v1);
                v2 = gelu_exact(v2); v3 = gelu_exact(v3);
            }
            if (OUTHALF) {
                __half* C = (__half*)Cv + strC * blockIdx.z;
                *(__half2*)&C[(size_t)r0 * ldC + col] =
                    __halves2half2(__float2half_rn(v0), __float2half_rn(v1));
                *(__half2*)&C[(size_t)r1 * ldC + col] =
                    __halves2half2(__float2half_rn(v2), __float2half_rn(v3));
            } else {
                float* C = (float*)Cv + strC * blockIdx.z;
                *(float2*)&C[(size_t)r0 * ldC + col] = make_float2(v0, v1);
                *(float2*)&C[(size_t)r1 * ldC + col] = make_float2(v2, v3);
            }
        }
    }
}

// ---------------- prep: transposes + x->fp16 + bias concat (one launch) -----
__global__ __launch_bounds__(256)
void prep(const float* __restrict__ x,
          const float* __restrict__ Wq, const float* __restrict__ Wk,
          const float* __restrict__ Wv, const float* __restrict__ W1,
          const float* __restrict__ W2,
          const float* __restrict__ bq, const float* __restrict__ bk,
          const float* __restrict__ bv,
          __half* __restrict__ xh, __half* __restrict__ WqkvT,
          __half* __restrict__ W1T, __half* __restrict__ W2T,
          float* __restrict__ bqkv)
{
    const int bid = blockIdx.x;
    const int tid = threadIdx.x;
    if (bid < 5120) {
        __shared__ float tile[32][33];
        const int z = bid >> 10;
        const int t = bid & 1023;
        const int c0 = (t & 31) * 32, r0 = (t >> 5) * 32;
        const float* in = (z == 0) ? Wq : (z == 1) ? Wk : (z == 2) ? Wv : (z == 3) ? W1 : W2;
        __half* out = (z == 0) ? WqkvT : (z == 1) ? (WqkvT + DD * DD)
                     : (z == 2) ? (WqkvT + 2 * DD * DD) : (z == 3) ? W1T : W2T;
        const int tx = tid & 31, ty = tid >> 5;   // 32 x 8
        #pragma unroll
        for (int i = 0; i < 4; i++)
            tile[ty + i * 8][tx] = in[(size_t)(r0 + ty + i * 8) * DD + c0 + tx];
        __syncthreads();
        #pragma unroll
        for (int i = 0; i < 4; i++)
            out[(size_t)(c0 + ty + i * 8) * DD + r0 + tx] =
                __float2half_rn(tile[tx][ty + i * 8]);
    } else if (bid < 13312) {
        size_t i = (size_t)(bid - 5120) * 256 + tid;     // float4 index
        float4 v = ((const float4*)x)[i];
        ((__half2*)xh)[i * 2]     = __halves2half2(__float2half_rn(v.x), __float2half_rn(v.y));
        ((__half2*)xh)[i * 2 + 1] = __halves2half2(__float2half_rn(v.z), __float2half_rn(v.w));
    } else {
        const int z = bid - 13312;
        const float* src = (z == 0) ? bq : (z == 1) ? bk : bv;
        for (int i = tid; i < DD; i += 256) bqkv[z * DD + i] = src[i];
    }
}

// final: out = LN(h2 + h) with fp16 inputs, fp32 math + output
__global__ __launch_bounds__(256)
void add_ln1024_hh(const __half* __restrict__ A, const __half* __restrict__ R,
                   const float* __restrict__ gamma, const float* __restrict__ beta,
                   float* __restrict__ out)
{
    const size_t row = blockIdx.x;
    const int t = threadIdx.x, lane = t & 31, wid = t >> 5;
    __shared__ float rs[8], rq[8];

    uint2 ar = ((const uint2*)(A + row * 1024))[t];
    uint2 rr = ((const uint2*)(R + row * 1024))[t];
    float2 a01 = __half22float2(*(__half2*)&ar.x);
    float2 a23 = __half22float2(*(__half2*)&ar.y);
    float2 r01 = __half22float2(*(__half2*)&rr.x);
    float2 r23 = __half22float2(*(__half2*)&rr.y);
    float h0 = a01.x + r01.x, h1 = a01.y + r01.y;
    float h2 = a23.x + r23.x, h3 = a23.y + r23.y;

    float s = h0 + h1 + h2 + h3;
    float q = h0 * h0 + h1 * h1 + h2 * h2 + h3 * h3;
    s = warp_sum(s); q = warp_sum(q);
    if (lane == 0) { rs[wid] = s; rq[wid] = q; }
    __syncthreads();
    s = rs[0]; q = rq[0];
    #pragma unroll
    for (int i = 1; i < 8; i++) { s += rs[i]; q += rq[i]; }

    const float mean = s * (1.0f / 1024.0f);
    const float var  = q * (1.0f / 1024.0f) - mean * mean;
    const float rstd = rsqrtf(var + LN_EPS);

    float4 gg = ((const float4*)gamma)[t];
    float4 bb = ((const float4*)beta)[t];
    float4 o;
    o.x = (h0 - mean) * rstd * gg.x + bb.x;
    o.y = (h1 - mean) * rstd * gg.y + bb.y;
    o.z = (h2 - mean) * rstd * gg.z + bb.z;
    o.w = (h3 - mean) * rstd * gg.w + bb.w;
    ((float4*)(out + row * 1024))[t] = o;
}

// fused: at = LN(Oh + xh)*gat+bat; Hh = fp16(LN(at + xh)*gln+bln)
__global__ __launch_bounds__(256)
void ln2_fused(const __half* __restrict__ Oh, const __half* __restrict__ Xh,
               const float* __restrict__ gat, const float* __restrict__ bat,
               const float* __restrict__ gln, const float* __restrict__ bln,
               __half* __restrict__ Hh)
{
    const size_t row = blockIdx.x;
    const int t = threadIdx.x, lane = t & 31, wid = t >> 5;
    __shared__ float rs[8], rq[8];

    uint2 orr = ((const uint2*)(Oh + row * 1024))[t];
    uint2 xrr = ((const uint2*)(Xh + row * 1024))[t];
    float2 o01 = __half22float2(*(__half2*)&orr.x);
    float2 o23 = __half22float2(*(__half2*)&orr.y);
    float2 x01 = __half22float2(*(__half2*)&xrr.x);
    float2 x23 = __half22float2(*(__half2*)&xrr.y);
    float xv[4] = {x01.x, x01.y, x23.x, x23.y};
    float h[4] = {o01.x + xv[0], o01.y + xv[1], o23.x + xv[2], o23.y + xv[3]};

    float s = h[0] + h[1] + h[2] + h[3];
    float q = h[0]*h[0] + h[1]*h[1] + h[2]*h[2] + h[3]*h[3];
    s = warp_sum(s); q = warp_sum(q);
    if (lane == 0) { rs[wid] = s; rq[wid] = q; }
    __syncthreads();
    s = rs[0]; q = rq[0];
    #pragma unroll
    for (int i = 1; i < 8; i++) { s += rs[i]; q += rq[i]; }
    float mean = s * (1.0f / 1024.0f);
    float var  = q * (1.0f / 1024.0f) - mean * mean;
    float rstd = rsqrtf(var + LN_EPS);

    float4 g1 = ((const float4*)gat)[t];
    float4 b1 = ((const float4*)bat)[t];
    float u[4];
    u[0] = (h[0] - mean) * rstd * g1.x + b1.x + xv[0];
    u[1] = (h[1] - mean) * rstd * g1.y + b1.y + xv[1];
    u[2] = (h[2] - mean) * rstd * g1.z + b1.z + xv[2];
    u[3] = (h[3] - mean) * rstd * g1.w + b1.w + xv[3];
    __syncthreads();

    s = u[0] + u[1] + u[2] + u[3];
    q = u[0]*u[0] + u[1]*u[1] + u[2]*u[2] + u[3]*u[3];
    s = warp_sum(s); q = warp_sum(q);
    if (lane == 0) { rs[wid] = s; rq[wid] = q; }
    __syncthreads();
    s = rs[0]; q = rq[0];
    #pragma unroll
    for (int i = 1; i < 8; i++) { s += rs[i]; q += rq[i]; }
    mean = s * (1.0f / 1024.0f);
    var  = q * (1.0f / 1024.0f) - mean * mean;
    rstd = rsqrtf(var + LN_EPS);

    float4 g2 = ((const float4*)gln)[t];
    float4 b2 = ((const float4*)bln)[t];
    float v0 = (u[0] - mean) * rstd * g2.x + b2.x;
    float v1 = (u[1] - mean) * rstd * g2.y + b2.y;
    float v2 = (u[2] - mean) * rstd * g2.z + b2.z;
    float v3 = (u[3] - mean) * rstd * g2.w + b2.w;
    uint2 hw;
    __half2 p01 = __halves2half2(__float2half_rn(v0), __float2half_rn(v1));
    __half2 p23 = __halves2half2(__float2half_rn(v2), __float2half_rn(v3));
    hw.x = *(uint32_t*)&p01; hw.y = *(uint32_t*)&p23;
    ((uint2*)(Hh + row * 1024))[t] = hw;
}

// ---------------- launcher ---------------------------------------------------
extern "C" void kernel_launch(void* const* d_in, const int* in_sizes, int n_in,
                              void* d_out, int out_size)
{
    const float* x   = (const float*)d_in[0];
    const float* Wq  = (const float*)d_in[1];
    const float* bq  = (const float*)d_in[2];
    const float* Wk  = (const float*)d_in[3];
    const float* bk  = (const float*)d_in[4];
    const float* Wv  = (const float*)d_in[5];
    const float* bv  = (const float*)d_in[6];
    const float* gat = (const float*)d_in[7];
    const float* bat = (const float*)d_in[8];
    const float* gln = (const float*)d_in[9];
    const float* bln = (const float*)d_in[10];
    const float* W1  = (const float*)d_in[11];
    const float* c1  = (const float*)d_in[12];
    const float* W2  = (const float*)d_in[13];
    const float* c2  = (const float*)d_in[14];
    float* out = (float*)d_out;

    __half *xh, *WqkvT, *W1T, *W2T, *QKVh, *Ph, *Oh, *Hh, *H1h, *H2h;
    float *bqkv, *rowpart;
    cudaGetSymbolAddress((void**)&xh,     g_xh);
    cudaGetSymbolAddress((void**)&WqkvT,  g_WqkvT);
    cudaGetSymbolAddress((void**)&W1T,    g_W1T);
    cudaGetSymbolAddress((void**)&W2T,    g_W2T);
    cudaGetSymbolAddress((void**)&bqkv,   g_bqkv);
    cudaGetSymbolAddress((void**)&QKVh,   g_QKVh);
    cudaGetSymbolAddress((void**)&Ph,     g_Ph);
    cudaGetSymbolAddress((void**)&rowpart,g_rowpart);
    cudaGetSymbolAddress((void**)&Oh,     g_Oh);
    cudaGetSymbolAddress((void**)&Hh,     g_Hh);
    cudaGetSymbolAddress((void**)&H1h,    g_H1h);
    cudaGetSymbolAddress((void**)&H2h,    g_H2h);

    cudaFuncSetAttribute(tgemm<0,1,0,0,0>, cudaFuncAttributeMaxDynamicSharedMemorySize, SMEM_BYTES);
    cudaFuncSetAttribute(tgemm<0,1,1,0,0>, cudaFuncAttributeMaxDynamicSharedMemorySize, SMEM_BYTES);
    cudaFuncSetAttribute(tgemm<0,1,0,1,1>, cudaFuncAttributeMaxDynamicSharedMemorySize, SMEM_BYTES);
    cudaFuncSetAttribute(tgemm<1,1,0,0,0>, cudaFuncAttributeMaxDynamicSharedMemorySize, SMEM_BYTES);

    const dim3 blk(256);
    const dim3 gblk(128);
    const size_t sSS = (size_t)SS * SS;

    // 1: prep (x->fp16, W transposes -> WqkvT/W1T/W2T, bias concat)
    prep<<<13315, blk>>>(x, Wq, Wk, Wv, W1, W2, bq, bk, bv,
                         xh, WqkvT, W1T, W2T, bqkv);

    // 2: merged QKV GEMM: [8192,3072] = xh @ WqkvT^T + bqkv
    tgemm<0,1,0,0,0><<<dim3(24, 64, 1), gblk, SMEM_BYTES>>>(
        xh, WqkvT, bqkv, QKVh, DD, DD, 3 * DD, DD, 1.0f, 0, 0, 0, nullptr);

    const __half* Qh = QKVh;
    const __half* Kh = QKVh + DD;
    const __half* Vh = QKVh + 2 * DD;

    // 3: scores GEMM with fused exp + row partials -> Ph (exp'd fp16)
    tgemm<0,1,1,0,0><<<dim3(16, 16, BB), gblk, SMEM_BYTES>>>(
        Qh, Kh, nullptr, Ph, 3 * DD, 3 * DD, SS, DD, INV_SCALE,
        (size_t)SS * 3 * DD, (size_t)SS * 3 * DD, sSS, rowpart);

    // 4: Oh = (Pexp @ V) / rowsum (fp16 out; V natural layout via ldmatrix.trans)
    tgemm<0,1,0,1,1><<<dim3(8, 16, BB), gblk, SMEM_BYTES>>>(
        Ph, Vh, nullptr, Oh, SS, 3 * DD, DD, SS, 1.0f,
        sSS, (size_t)SS * 3 * DD, (size_t)SS * DD, rowpart);

    // 5: fused double-LN -> Hh (fp16 in/out; x residual from xh)
    ln2_fused<<<MTOT, blk>>>(Oh, xh, gat, bat, gln, bln, Hh);

    // 6-7: FFN
    tgemm<1,1,0,0,0><<<dim3(8, 64, 1), gblk, SMEM_BYTES>>>(
        Hh,  W1T, c1, H1h, DD, DD, DD, DD, 1.0f, 0, 0, 0, nullptr);
    tgemm<1,1,0,0,0><<<dim3(8, 64, 1), gblk, SMEM_BYTES>>>(
        H1h, W2T, c2, H2h, DD, DD, DD, DD, 1.0f, 0, 0, 0, nullptr);

    // 8: out = LN(h2 + h), fp16 inputs, fp32 output
    add_ln1024_hh<<<MTOT, blk>>>(H2h, Hh, gln, bln, out);
}